// round 10
// baseline (speedup 1.0000x reference)
#include <cuda_runtime.h>
#include <cuda_fp16.h>
#include <cstdint>

#define HH 128
#define WW 256
#define HWP 32768
#define CC 64
#define BB 2
#define KK 16
#define CHW (CC * HWP)

typedef unsigned long long u64;
typedef unsigned int u32;

// ---------------- scratch ----------------------------------------------------
__device__ u32 g_xs[4 * HWP * CC];     // packed {hi16,lo16} fp16 split of x, pixel-major
__device__ u32 g_ts[4 * HWP * CC];     // packed split of conv1 output, pixel-major
__device__ float g_buf[4 * CHW];       // conv2 output (fp32, channel-major)
__device__ float g_Q[BB * HWP * CC];
__device__ float g_S[BB * HWP * CC];
__device__ float g_R[BB * HWP * CC];
__device__ float g_battn[BB * HWP * CC];
__device__ u64 g_wf[2 * 9 * 2 * 4 * 8 * 32];  // conv B-frags, pair-ordered (36864)
__device__ u64 g_wq[3][4096];                 // qsr dup-packed
__device__ u64 g_wfu[8192];                   // fuse dup-packed

// ---------------- f32x2 helpers ----------------------------------------------
__device__ __forceinline__ u64 pk2(float lo, float hi) {
    u64 r;
    asm("mov.b64 %0, {%1, %2};" : "=l"(r) : "f"(lo), "f"(hi));
    return r;
}
__device__ __forceinline__ void upk2(u64 v, float& lo, float& hi) {
    asm("mov.b64 {%0, %1}, %2;" : "=f"(lo), "=f"(hi) : "l"(v));
}
__device__ __forceinline__ u64 fma2(u64 a, u64 b, u64 c) {
    u64 d;
    asm("fma.rn.f32x2 %0, %1, %2, %3;" : "=l"(d) : "l"(a), "l"(b), "l"(c));
    return d;
}

// ---------------- fp16 split helpers ------------------------------------------
__device__ __forceinline__ u32 splitpack(float v) {
    __half h = __float2half_rn(v);
    __half l = __float2half_rn(v - __half2float(h));
    return (u32)__half_as_ushort(h) | ((u32)__half_as_ushort(l) << 16);
}

// ---------------- mma / ldmatrix ----------------------------------------------
__device__ __forceinline__ void mma16816(float c[4], const u32 a[4], u32 b0, u32 b1) {
    asm volatile(
        "mma.sync.aligned.m16n8k16.row.col.f32.f16.f16.f32 "
        "{%0,%1,%2,%3},{%4,%5,%6,%7},{%8,%9},{%0,%1,%2,%3};"
        : "+f"(c[0]), "+f"(c[1]), "+f"(c[2]), "+f"(c[3])
        : "r"(a[0]), "r"(a[1]), "r"(a[2]), "r"(a[3]), "r"(b0), "r"(b1));
}
__device__ __forceinline__ void ldsm4(u32 r[4], u32 addr) {
    asm volatile("ldmatrix.sync.aligned.m8n8.x4.shared.b16 {%0,%1,%2,%3}, [%4];"
                 : "=r"(r[0]), "=r"(r[1]), "=r"(r[2]), "=r"(r[3])
                 : "r"(addr));
}
__device__ __forceinline__ u32 smem_u32(const void* p) {
    u32 a;
    asm("{ .reg .u64 t; cvta.to.shared.u64 t, %1; cvt.u32.u64 %0, t; }" : "=r"(a) : "l"(p));
    return a;
}

// ---------------- prep: weights ------------------------------------------------
// conv fragments, pair-ordered: [conv][tap][split][k][np][lane][e]
__global__ void __launch_bounds__(256) prep_w(const float* __restrict__ w1,
                                              const float* __restrict__ w2,
                                              const float* __restrict__ qw,
                                              const float* __restrict__ sw,
                                              const float* __restrict__ rw,
                                              const float* __restrict__ fw) {
    int i = blockIdx.x * 256 + threadIdx.x;  // 0..57343
    if (i < 36864) {
        int conv = i / 18432;
        int r = i % 18432;
        int tap = r / 2048;
        int r2 = r % 2048;
        int split = (r2 >> 10) & 1;
        int k = (r2 >> 8) & 3;
        int low8 = r2 & 255;
        int np = low8 >> 6;
        int lane = (low8 >> 1) & 31;
        int e = low8 & 1;
        int n = np * 2 + e;
        int g = lane >> 2, tig = lane & 3;
        int cin0 = k * 16 + 2 * tig;
        int co = n * 8 + g;
        const float* w = conv ? w2 : w1;
        unsigned short hv[4];
#pragma unroll
        for (int en = 0; en < 4; en++) {
            int cin = cin0 + (en & 1) + (en >> 1) * 8;
            float v = w[(co * 64 + cin) * 9 + tap];
            __half h = __float2half_rn(v);
            __half o = split ? __float2half_rn(v - __half2float(h)) : h;
            hv[en] = __half_as_ushort(o);
        }
        u32 b0 = (u32)hv[0] | ((u32)hv[1] << 16);
        u32 b1 = (u32)hv[2] | ((u32)hv[3] << 16);
        g_wf[i] = (u64)b0 | ((u64)b1 << 32);
    } else if (i < 49152) {
        int j = i - 36864;
        int mat = j >> 12;
        int e = j & 4095;
        int cin = e >> 6, co = e & 63;
        const float* w = (mat == 0) ? qw : (mat == 1) ? sw : rw;
        float v = w[co * 64 + cin];
        g_wq[mat][e] = pk2(v, v);
    } else {
        int j = i - 49152;
        int cin = j >> 6, co = j & 63;
        float v = fw[co * 128 + cin];
        g_wfu[j] = pk2(v, v);
    }
}

// ---------------- prep: split x into pixel-major packed u32 -------------------
__global__ void __launch_bounds__(256) prep_x(const float* __restrict__ xl,
                                              const float* __restrict__ xr) {
    __shared__ float tile[64 * 65];
    const int t = threadIdx.x;
    const int img = blockIdx.x >> 9;
    const int px0 = (blockIdx.x & 511) * 64;
    const float* in = (img < 2) ? (xl + img * CHW) : (xr + (img - 2) * CHW);

    for (int i = t; i < 4096; i += 256) {
        int cin = i >> 6, px = i & 63;
        tile[px * 65 + cin] = in[cin * HWP + px0 + px];
    }
    __syncthreads();
    for (int i = t; i < 4096; i += 256) {
        int px = i >> 6, cin = i & 63;
        g_xs[(img * HWP + px0 + px) * 64 + cin] = splitpack(tile[px * 65 + cin]);
    }
}

// ---------------- conv3x3 via mma.sync + ldmatrix + smem-B --------------------
// CTA = 256 thr (8 warps): one 64-px strip x 64 couts. 2 CTAs/SM.
// Warp: pq = w&3 -> 16 px, ch = w>>2 -> 32 couts (4 n-tiles).
// smem: AH plane [3 rows][66 px][128 B, XOR-swizzled], AL plane, 2x16KB B bufs.
#define APLANE 25344                       // 3*66*128
#define BOFF (2 * APLANE)                  // 50688
#define CONV_SMEM (BOFF + 2 * 16384)       // 83456

template <int MODE>
__global__ void __launch_bounds__(256, 2) conv_mma(const float* __restrict__ xl,
                                                   const float* __restrict__ xr) {
    extern __shared__ unsigned char sm[];
    const u32 smb = smem_u32(sm);
    const int t = threadIdx.x;
    const int w = t >> 5;
    const int lane = t & 31;
    const int g = lane >> 2, tig = lane & 3;
    const int pq = w & 3, ch = w >> 2;

    const int blk = blockIdx.x;            // 0..2047
    const int img = blk >> 9;
    const int rr = blk & 511;
    const int y = rr >> 2;
    const int x0 = (rr & 3) * 64;

    const u32* inp = ((MODE == 0) ? g_xs : g_ts) + img * HWP * 64;

    // ---- stage A: 3 rows x 66 px x 64 cin, split into hi/lo planes ----
    for (int i = t; i < 1584; i += 256) {
        int gr = i & 7;
        int pxr = i >> 3;                  // 0..197
        int r = pxr / 66, apx = pxr - r * 66;
        int gy = y - 1 + r, gx = x0 - 1 + apx;
        uint4 a = make_uint4(0, 0, 0, 0), b = make_uint4(0, 0, 0, 0);
        if ((unsigned)gy < HH && (unsigned)gx < WW) {
            const uint4* src = (const uint4*)(inp + (gy * WW + gx) * 64 + gr * 8);
            a = src[0];
            b = src[1];
        }
        uint4 hv, lv;
        hv.x = __byte_perm(a.x, a.y, 0x5410);
        hv.y = __byte_perm(a.z, a.w, 0x5410);
        hv.z = __byte_perm(b.x, b.y, 0x5410);
        hv.w = __byte_perm(b.z, b.w, 0x5410);
        lv.x = __byte_perm(a.x, a.y, 0x7632);
        lv.y = __byte_perm(a.z, a.w, 0x7632);
        lv.z = __byte_perm(b.x, b.y, 0x7632);
        lv.w = __byte_perm(b.z, b.w, 0x7632);
        int base = (r * 66 + apx) * 128 + ((gr * 16) ^ ((apx & 7) << 4));
        *(uint4*)(sm + base) = hv;
        *(uint4*)(sm + APLANE + base) = lv;
    }
    // ---- stage B tap 0 (1024 uint4) ----
    {
        const uint4* src = (const uint4*)(g_wf + (MODE * 9) * 2048);
        uint4* dst = (uint4*)(sm + BOFF);
#pragma unroll
        for (int j = 0; j < 4; j++) dst[t * 4 + j] = src[t * 4 + j];
    }
    __syncthreads();

    const int m = lane >> 3;
    const int rowsel = (lane & 7) + ((m & 1) << 3);
    const int colbase = (m >> 1) * 16;

    float acc[4][4];
#pragma unroll
    for (int n = 0; n < 4; n++)
#pragma unroll
        for (int c = 0; c < 4; c++) acc[n][c] = 0.f;

#pragma unroll
    for (int tap = 0; tap < 9; tap++) {
        // prefetch next tap's B into the other buffer
        if (tap < 8) {
            const uint4* src = (const uint4*)(g_wf + (MODE * 9 + tap + 1) * 2048);
            uint4* dst = (uint4*)(sm + BOFF + ((tap + 1) & 1) * 16384);
#pragma unroll
            for (int j = 0; j < 4; j++) dst[t * 4 + j] = src[t * 4 + j];
        }
        const int dy = tap / 3, dx = tap - dy * 3;
        const int apx = pq * 16 + rowsel + dx;
        const u32 abase = smb + (dy * 66 + apx) * 128;
        const u32 sw = (u32)((apx & 7) << 4);
        const unsigned char* bbuf = sm + BOFF + (tap & 1) * 16384;

#pragma unroll
        for (int kk = 0; kk < 4; kk++) {
            u32 ah[4], al[4];
            u32 col = ((u32)(kk * 32 + colbase)) ^ sw;
            ldsm4(ah, abase + col);
            ldsm4(al, abase + APLANE + col);
#pragma unroll
            for (int j = 0; j < 2; j++) {
                const int np = 2 * ch + j;
                uint4 bh = *(const uint4*)(bbuf + kk * 2048 + np * 512 + lane * 16);
                uint4 bl = *(const uint4*)(bbuf + 8192 + kk * 2048 + np * 512 + lane * 16);
                mma16816(acc[2 * j], ah, bh.x, bh.y);
                mma16816(acc[2 * j], ah, bl.x, bl.y);
                mma16816(acc[2 * j], al, bh.x, bh.y);
                mma16816(acc[2 * j + 1], ah, bh.z, bh.w);
                mma16816(acc[2 * j + 1], ah, bl.z, bl.w);
                mma16816(acc[2 * j + 1], al, bh.z, bh.w);
            }
        }
        __syncthreads();
    }

    const int bp = y * WW + x0 + pq * 16 + g;  // pixel row g; +8 for row g+8
    if (MODE == 0) {
        u32* o0 = g_ts + (img * HWP + bp) * 64;
        u32* o1 = o0 + 8 * 64;
#pragma unroll
        for (int n = 0; n < 4; n++) {
            const int co0 = ch * 32 + n * 8 + 2 * tig;
            float v0 = acc[n][0], v1 = acc[n][1], v2 = acc[n][2], v3 = acc[n][3];
            v0 = v0 > 0.f ? v0 : 0.1f * v0;
            v1 = v1 > 0.f ? v1 : 0.1f * v1;
            v2 = v2 > 0.f ? v2 : 0.1f * v2;
            v3 = v3 > 0.f ? v3 : 0.1f * v3;
            u32 p0 = splitpack(v0), p1 = splitpack(v1);
            u32 p2 = splitpack(v2), p3 = splitpack(v3);
            *(u64*)(o0 + co0) = (u64)p0 | ((u64)p1 << 32);
            *(u64*)(o1 + co0) = (u64)p2 | ((u64)p3 << 32);
        }
    } else {
        const float* res = (img < 2) ? (xl + img * CHW) : (xr + (img - 2) * CHW);
        float* ob = g_buf + img * CHW;
#pragma unroll
        for (int n = 0; n < 4; n++) {
            const int co0 = ch * 32 + n * 8 + 2 * tig;
            ob[co0 * HWP + bp] = acc[n][0] + res[co0 * HWP + bp];
            ob[(co0 + 1) * HWP + bp] = acc[n][1] + res[(co0 + 1) * HWP + bp];
            ob[co0 * HWP + bp + 8] = acc[n][2] + res[co0 * HWP + bp + 8];
            ob[(co0 + 1) * HWP + bp + 8] = acc[n][3] + res[(co0 + 1) * HWP + bp + 8];
        }
    }
}

// ---------------- Q/S/R 1x1: smem-staged GEMM ---------------------------------
#define QSR_SMEM (32768 + 17408)
__global__ void __launch_bounds__(256, 2) qsr_k(const float* __restrict__ b1b,
                                                const float* __restrict__ b2b,
                                                const float* __restrict__ b3b) {
    extern __shared__ unsigned char dynsm[];
    u64* wsm = (u64*)dynsm;
    float* tile = (float*)(dynsm + 32768);
    float* st = (float*)(dynsm + 32768);

    const int t = threadIdx.x;
    const int mat = blockIdx.y;
    const int p0 = blockIdx.x * 256;
    const int b = p0 >> 15;
    const int lp = p0 & 32767;

    const float* in = g_buf + (((mat == 0) ? 0 : 2) + b) * CHW + lp;
    float* outp = ((mat == 0) ? g_Q : (mat == 1) ? g_S : g_R) + p0 * 64;
    const float* bias = (mat == 0) ? b1b : (mat == 1) ? b2b : b3b;

    {
        const u64* ws = g_wq[mat];
        for (int j = t; j < 4096; j += 256) wsm[j] = ws[j];
    }

    const int cg = t >> 5;
    const int tx = t & 31;

    u64 acc[8][4];
#pragma unroll
    for (int co = 0; co < 8; co++)
#pragma unroll
        for (int j = 0; j < 4; j++) acc[co][j] = 0ull;

    for (int cc0 = 0; cc0 < 64; cc0 += 16) {
        __syncthreads();
#pragma unroll
        for (int k = 0; k < 16; k++) {
            int j = t + k * 256;
            int cin = j >> 8, px = j & 255;
            tile[j] = in[(cc0 + cin) * HWP + px];
        }
        __syncthreads();
#pragma unroll 4
        for (int ci = 0; ci < 16; ci++) {
            u64 v[4];
#pragma unroll
            for (int j = 0; j < 4; j++) v[j] = *(const u64*)&tile[ci * 256 + 2 * tx + 64 * j];
            const u64* wb = wsm + (cc0 + ci) * 64 + cg * 8;
#pragma unroll
            for (int co = 0; co < 8; co++) {
                u64 w2 = wb[co];
#pragma unroll
                for (int j = 0; j < 4; j++) acc[co][j] = fma2(w2, v[j], acc[co][j]);
            }
        }
    }

#pragma unroll
    for (int j = 0; j < 4; j++) {
        __syncthreads();
#pragma unroll
        for (int co = 0; co < 8; co++) {
            float lo, hi;
            upk2(acc[co][j], lo, hi);
            st[(2 * tx) * 65 + cg * 8 + co] = lo;
            st[(2 * tx + 1) * 65 + cg * 8 + co] = hi;
        }
        __syncthreads();
        for (int i = t; i < 4096; i += 256) {
            int px = i >> 6, c = i & 63;
            outp[(64 * j + px) * 64 + c] = st[px * 65 + c] + bias[c];
        }
    }
}

// ---------------- attention: warp per pixel ----------------------------------
__global__ void __launch_bounds__(256) attn_k(const int* __restrict__ xxs,
                                              const int* __restrict__ yys,
                                              float* __restrict__ Mout) {
    const int t = threadIdx.x;
    const int lane = t & 31;
    const int p = blockIdx.x * 8 + (t >> 5);
    const int b = p >> 15;

    int fl = 0;
    if (lane < 16) fl = xxs[p * 16 + lane] * WW + yys[p * 16 + lane];

    const float q0 = g_Q[p * 64 + lane];
    const float q1 = g_Q[p * 64 + lane + 32];
    const float* Sb = g_S + b * HWP * 64;
    const float* Rb = g_R + b * HWP * 64;

    float sc[16];
    int bs[16];
#pragma unroll
    for (int k = 0; k < 16; k++) {
        int fk = __shfl_sync(0xffffffffu, fl, k);
        int base = fk * 64;
        bs[k] = base;
        float part = q0 * Sb[base + lane] + q1 * Sb[base + lane + 32];
#pragma unroll
        for (int o = 16; o; o >>= 1) part += __shfl_xor_sync(0xffffffffu, part, o);
        sc[k] = part;
    }

    float mx = sc[0];
#pragma unroll
    for (int k = 1; k < 16; k++) mx = fmaxf(mx, sc[k]);
    float sum = 0.f;
#pragma unroll
    for (int k = 0; k < 16; k++) {
        sc[k] = __expf(sc[k] - mx);
        sum += sc[k];
    }
    const float inv = 1.f / sum;

    float acc0 = 0.f, acc1 = 0.f, mv = 0.f;
#pragma unroll
    for (int k = 0; k < 16; k++) {
        float m = sc[k] * inv;
        acc0 += m * Rb[bs[k] + lane];
        acc1 += m * Rb[bs[k] + lane + 32];
        if (lane == k) mv = m;
    }

    g_battn[p * 64 + lane] = acc0;
    g_battn[p * 64 + lane + 32] = acc1;
    if (lane < 16) Mout[p * 16 + lane] = mv;
}

// ---------------- fusion 1x1 ---------------------------------------------------
#define FUSE_SMEM (65536 + 8448)
__global__ void __launch_bounds__(256) fuse_k(const float* __restrict__ xl,
                                              const float* __restrict__ fb,
                                              float* __restrict__ out) {
    extern __shared__ unsigned char dynsm[];
    u64* wsm = (u64*)dynsm;
    float* vsm = (float*)(dynsm + 65536);

    const int t = threadIdx.x;
    const int b = blockIdx.y;
    const int p0 = blockIdx.x * 256;

    for (int j = t; j < 8192; j += 256) wsm[j] = g_wfu[j];

    const float* ba = g_battn + b * HWP * 64;
    const float* xlb = xl + b * CHW;
    const int cg = t >> 6, q = t & 63;
    u64 acc[16][2];
#pragma unroll
    for (int c = 0; c < 16; c++) {
        acc[c][0] = 0ull;
        acc[c][1] = 0ull;
    }
    __syncthreads();

    for (int cc0 = 0; cc0 < 64; cc0 += 8) {
        __syncthreads();
        for (int i = t; i < 2048; i += 256) {
            int c = i & 7, px = i >> 3;
            vsm[c * 258 + px] = ba[(p0 + px) * 64 + cc0 + c];
        }
        __syncthreads();
#pragma unroll
        for (int cl = 0; cl < 8; cl++) {
            const int cin = cc0 + cl;
            u64 v0 = *(const u64*)&vsm[cl * 258 + 2 * q];
            u64 v1 = *(const u64*)&vsm[cl * 258 + 128 + 2 * q];
            const u64* wb = wsm + cin * 64 + cg * 16;
#pragma unroll
            for (int c = 0; c < 16; c++) {
                u64 w2 = wb[c];
                acc[c][0] = fma2(w2, v0, acc[c][0]);
                acc[c][1] = fma2(w2, v1, acc[c][1]);
            }
        }
    }
#pragma unroll 4
    for (int cin = 64; cin < 128; cin++) {
        u64 v0 = *(const u64*)(xlb + (cin - 64) * HWP + p0 + 2 * q);
        u64 v1 = *(const u64*)(xlb + (cin - 64) * HWP + p0 + 128 + 2 * q);
        const u64* wb = wsm + cin * 64 + cg * 16;
#pragma unroll
        for (int c = 0; c < 16; c++) {
            u64 w2 = wb[c];
            acc[c][0] = fma2(w2, v0, acc[c][0]);
            acc[c][1] = fma2(w2, v1, acc[c][1]);
        }
    }

#pragma unroll
    for (int c = 0; c < 16; c++) {
        const int co = cg * 16 + c;
        const float bb = fb[co];
#pragma unroll
        for (int r = 0; r < 2; r++) {
            float lo, hi;
            upk2(acc[c][r], lo, hi);
            float2 o;
            o.x = lo + bb;
            o.y = hi + bb;
            *(float2*)(out + (b * 64 + co) * HWP + p0 + 128 * r + 2 * q) = o;
        }
    }
}

// ---------------- launch ------------------------------------------------------
extern "C" void kernel_launch(void* const* d_in, const int* in_sizes, int n_in,
                              void* d_out, int out_size) {
    const float* xl = (const float*)d_in[0];
    const float* xr = (const float*)d_in[1];
    const int* xxs = (const int*)d_in[2];
    const int* yys = (const int*)d_in[3];
    const int wbase = (in_sizes[4] == 1) ? 5 : 4;
    const float* rb_w1 = (const float*)d_in[wbase + 0];
    const float* rb_w2 = (const float*)d_in[wbase + 1];
    const float* b1w = (const float*)d_in[wbase + 2];
    const float* b1b = (const float*)d_in[wbase + 3];
    const float* b2w = (const float*)d_in[wbase + 4];
    const float* b2b = (const float*)d_in[wbase + 5];
    const float* b3w = (const float*)d_in[wbase + 6];
    const float* b3b = (const float*)d_in[wbase + 7];
    const float* fw = (const float*)d_in[wbase + 8];
    const float* fb = (const float*)d_in[wbase + 9];

    float* out = (float*)d_out;
    float* Mout = out + BB * CC * HWP;

    cudaFuncSetAttribute(conv_mma<0>, cudaFuncAttributeMaxDynamicSharedMemorySize, CONV_SMEM);
    cudaFuncSetAttribute(conv_mma<1>, cudaFuncAttributeMaxDynamicSharedMemorySize, CONV_SMEM);
    cudaFuncSetAttribute(qsr_k, cudaFuncAttributeMaxDynamicSharedMemorySize, QSR_SMEM);
    cudaFuncSetAttribute(fuse_k, cudaFuncAttributeMaxDynamicSharedMemorySize, FUSE_SMEM);

    prep_w<<<224, 256>>>(rb_w1, rb_w2, b1w, b2w, b3w, fw);
    prep_x<<<2048, 256>>>(xl, xr);

    conv_mma<0><<<2048, 256, CONV_SMEM>>>(xl, xr);
    conv_mma<1><<<2048, 256, CONV_SMEM>>>(xl, xr);

    qsr_k<<<dim3(BB * HWP / 256, 3), 256, QSR_SMEM>>>(b1b, b2b, b3b);

    attn_k<<<BB * HWP / 8, 256>>>(xxs, yys, Mout);

    fuse_k<<<dim3(HWP / 256, BB), 256, FUSE_SMEM>>>(xl, fb, out);
}

// round 11
// speedup vs baseline: 1.5220x; 1.5220x over previous
#include <cuda_runtime.h>
#include <cuda_fp16.h>
#include <cstdint>

#define HH 128
#define WW 256
#define HWP 32768
#define CC 64
#define BB 2
#define KK 16
#define CHW (CC * HWP)

typedef unsigned long long u64;
typedef unsigned int u32;

// ---------------- scratch ----------------------------------------------------
__device__ u32 g_xs[4 * HWP * CC];     // packed {hi16,lo16} fp16 split of x, pixel-major
__device__ u32 g_ts[4 * HWP * CC];     // packed split of conv1 output, pixel-major
__device__ float g_buf[4 * CHW];       // conv2 output (fp32, channel-major)
__device__ float g_Q[BB * HWP * CC];
__device__ float g_S[BB * HWP * CC];
__device__ float g_R[BB * HWP * CC];
__device__ float g_battn[BB * HWP * CC];
__device__ u64 g_wf[2 * 9 * 2 * 4 * 8 * 32];  // conv B-frags, pair-ordered (36864)
__device__ u64 g_wq[3][4096];                 // qsr dup-packed
__device__ u64 g_wfu[8192];                   // fuse dup-packed

// ---------------- f32x2 helpers ----------------------------------------------
__device__ __forceinline__ u64 pk2(float lo, float hi) {
    u64 r;
    asm("mov.b64 %0, {%1, %2};" : "=l"(r) : "f"(lo), "f"(hi));
    return r;
}
__device__ __forceinline__ void upk2(u64 v, float& lo, float& hi) {
    asm("mov.b64 {%0, %1}, %2;" : "=f"(lo), "=f"(hi) : "l"(v));
}
__device__ __forceinline__ u64 fma2(u64 a, u64 b, u64 c) {
    u64 d;
    asm("fma.rn.f32x2 %0, %1, %2, %3;" : "=l"(d) : "l"(a), "l"(b), "l"(c));
    return d;
}

// ---------------- fp16 split helpers ------------------------------------------
__device__ __forceinline__ u32 splitpack(float v) {
    __half h = __float2half_rn(v);
    __half l = __float2half_rn(v - __half2float(h));
    return (u32)__half_as_ushort(h) | ((u32)__half_as_ushort(l) << 16);
}

// ---------------- mma / ldmatrix ----------------------------------------------
__device__ __forceinline__ void mma16816(float c[4], const u32 a[4], u32 b0, u32 b1) {
    asm volatile(
        "mma.sync.aligned.m16n8k16.row.col.f32.f16.f16.f32 "
        "{%0,%1,%2,%3},{%4,%5,%6,%7},{%8,%9},{%0,%1,%2,%3};"
        : "+f"(c[0]), "+f"(c[1]), "+f"(c[2]), "+f"(c[3])
        : "r"(a[0]), "r"(a[1]), "r"(a[2]), "r"(a[3]), "r"(b0), "r"(b1));
}
__device__ __forceinline__ void ldsm4(u32 r[4], u32 addr) {
    asm volatile("ldmatrix.sync.aligned.m8n8.x4.shared.b16 {%0,%1,%2,%3}, [%4];"
                 : "=r"(r[0]), "=r"(r[1]), "=r"(r[2]), "=r"(r[3])
                 : "r"(addr));
}
__device__ __forceinline__ u32 smem_u32(const void* p) {
    u32 a;
    asm("{ .reg .u64 t; cvta.to.shared.u64 t, %1; cvt.u32.u64 %0, t; }" : "=r"(a) : "l"(p));
    return a;
}

// ---------------- prep: weights ------------------------------------------------
// conv fragments, pair-ordered: [conv][tap][split][k][np][lane][e]
__global__ void __launch_bounds__(256) prep_w(const float* __restrict__ w1,
                                              const float* __restrict__ w2,
                                              const float* __restrict__ qw,
                                              const float* __restrict__ sw,
                                              const float* __restrict__ rw,
                                              const float* __restrict__ fw) {
    int i = blockIdx.x * 256 + threadIdx.x;  // 0..57343
    if (i < 36864) {
        int conv = i / 18432;
        int r = i % 18432;
        int tap = r / 2048;
        int r2 = r % 2048;
        int split = (r2 >> 10) & 1;
        int k = (r2 >> 8) & 3;
        int low8 = r2 & 255;
        int np = low8 >> 6;
        int lane = (low8 >> 1) & 31;
        int e = low8 & 1;
        int n = np * 2 + e;
        int g = lane >> 2, tig = lane & 3;
        int cin0 = k * 16 + 2 * tig;
        int co = n * 8 + g;
        const float* w = conv ? w2 : w1;
        unsigned short hv[4];
#pragma unroll
        for (int en = 0; en < 4; en++) {
            int cin = cin0 + (en & 1) + (en >> 1) * 8;
            float v = w[(co * 64 + cin) * 9 + tap];
            __half h = __float2half_rn(v);
            __half o = split ? __float2half_rn(v - __half2float(h)) : h;
            hv[en] = __half_as_ushort(o);
        }
        u32 b0 = (u32)hv[0] | ((u32)hv[1] << 16);
        u32 b1 = (u32)hv[2] | ((u32)hv[3] << 16);
        g_wf[i] = (u64)b0 | ((u64)b1 << 32);
    } else if (i < 49152) {
        int j = i - 36864;
        int mat = j >> 12;
        int e = j & 4095;
        int cin = e >> 6, co = e & 63;
        const float* w = (mat == 0) ? qw : (mat == 1) ? sw : rw;
        float v = w[co * 64 + cin];
        g_wq[mat][e] = pk2(v, v);
    } else {
        int j = i - 49152;
        int cin = j >> 6, co = j & 63;
        float v = fw[co * 128 + cin];
        g_wfu[j] = pk2(v, v);
    }
}

// ---------------- prep: split x into pixel-major packed u32 -------------------
__global__ void __launch_bounds__(256) prep_x(const float* __restrict__ xl,
                                              const float* __restrict__ xr) {
    __shared__ float tile[64 * 65];
    const int t = threadIdx.x;
    const int img = blockIdx.x >> 9;
    const int px0 = (blockIdx.x & 511) * 64;
    const float* in = (img < 2) ? (xl + img * CHW) : (xr + (img - 2) * CHW);

    for (int i = t; i < 4096; i += 256) {
        int cin = i >> 6, px = i & 63;
        tile[px * 65 + cin] = in[cin * HWP + px0 + px];
    }
    __syncthreads();
    for (int i = t; i < 4096; i += 256) {
        int px = i >> 6, cin = i & 63;
        g_xs[(img * HWP + px0 + px) * 64 + cin] = splitpack(tile[px * 65 + cin]);
    }
}

// ---------------- conv3x3: mma.sync, A in smem (ldsm), B via L1 LDG -----------
// CTA = 256 thr (8 warps), 128-px strip x 64 co. 2 CTAs/SM.
// Warp: pq = w&3 -> 32-px quarter (two 16-px m-tiles), ch = w>>2 -> 32-co half.
#define APLANE (3 * 130 * 128)        // 49920
#define CONV_SMEM (2 * APLANE)        // 99840

template <int MODE>
__global__ void __launch_bounds__(256, 2) conv_mma(const float* __restrict__ xl,
                                                   const float* __restrict__ xr) {
    extern __shared__ unsigned char sm[];
    const u32 smb = smem_u32(sm);
    const int t = threadIdx.x;
    const int w = t >> 5;
    const int lane = t & 31;
    const int g = lane >> 2, tig = lane & 3;
    const int pq = w & 3, ch = w >> 2;

    const int blk = blockIdx.x;            // 0..1023
    const int img = blk >> 8;
    const int rr = blk & 255;
    const int y = rr >> 1;
    const int x0 = (rr & 1) * 128;

    const u32* inp = ((MODE == 0) ? g_xs : g_ts) + img * HWP * 64;

    // ---- stage A: 3 rows x 130 px x 64 cin, hi/lo planes, XOR-swizzled ----
    for (int i = t; i < 3120; i += 256) {
        int gr = i & 7;
        int pxr = i >> 3;                  // 0..389
        int r = pxr / 130, apx = pxr - r * 130;
        int gy = y - 1 + r, gx = x0 - 1 + apx;
        uint4 a = make_uint4(0, 0, 0, 0), b = make_uint4(0, 0, 0, 0);
        if ((unsigned)gy < HH && (unsigned)gx < WW) {
            const uint4* src = (const uint4*)(inp + (gy * WW + gx) * 64 + gr * 8);
            a = src[0];
            b = src[1];
        }
        uint4 hv, lv;
        hv.x = __byte_perm(a.x, a.y, 0x5410);
        hv.y = __byte_perm(a.z, a.w, 0x5410);
        hv.z = __byte_perm(b.x, b.y, 0x5410);
        hv.w = __byte_perm(b.z, b.w, 0x5410);
        lv.x = __byte_perm(a.x, a.y, 0x7632);
        lv.y = __byte_perm(a.z, a.w, 0x7632);
        lv.z = __byte_perm(b.x, b.y, 0x7632);
        lv.w = __byte_perm(b.z, b.w, 0x7632);
        int base = (r * 130 + apx) * 128 + ((gr * 16) ^ ((apx & 7) << 4));
        *(uint4*)(sm + base) = hv;
        *(uint4*)(sm + APLANE + base) = lv;
    }
    __syncthreads();

    const int m = lane >> 3;
    const int rowsel = (lane & 7) + ((m & 1) << 3);
    const int colbase = (m >> 1) * 16;

    float acc[2][4][4];
#pragma unroll
    for (int mt = 0; mt < 2; mt++)
#pragma unroll
        for (int n = 0; n < 4; n++)
#pragma unroll
            for (int c = 0; c < 4; c++) acc[mt][n][c] = 0.f;

#pragma unroll
    for (int tap = 0; tap < 9; tap++) {
        const int dy = tap / 3, dx = tap - dy * 3;
        const int apx0 = pq * 32 + rowsel + dx;          // m-tile 0 px row
        const u32 ab0 = smb + (dy * 130 + apx0) * 128;
        const u32 ab1 = ab0 + 16 * 128;                  // m-tile 1 (+16 px)
        const u32 sw = (u32)((apx0 & 7) << 4);           // same for both (+16 keeps &7)
        const u64* WT = g_wf + (MODE * 9 + tap) * 2048 + lane * 2;

#pragma unroll
        for (int kk = 0; kk < 4; kk++) {
            u32 col = ((u32)(kk * 32 + colbase)) ^ sw;
            u32 ah0[4], al0[4], ah1[4], al1[4];
            ldsm4(ah0, ab0 + col);
            ldsm4(al0, ab0 + APLANE + col);
            ldsm4(ah1, ab1 + col);
            ldsm4(al1, ab1 + APLANE + col);
            const u64* WH = WT + kk * 256;
#pragma unroll
            for (int j = 0; j < 2; j++) {
                const u64* p = WH + (2 * ch + j) * 64;
                uint4 bh = *(const uint4*)p;
                uint4 bl = *(const uint4*)(p + 1024);
                mma16816(acc[0][2 * j], ah0, bh.x, bh.y);
                mma16816(acc[0][2 * j], ah0, bl.x, bl.y);
                mma16816(acc[0][2 * j], al0, bh.x, bh.y);
                mma16816(acc[0][2 * j + 1], ah0, bh.z, bh.w);
                mma16816(acc[0][2 * j + 1], ah0, bl.z, bl.w);
                mma16816(acc[0][2 * j + 1], al0, bh.z, bh.w);
                mma16816(acc[1][2 * j], ah1, bh.x, bh.y);
                mma16816(acc[1][2 * j], ah1, bl.x, bl.y);
                mma16816(acc[1][2 * j], al1, bh.x, bh.y);
                mma16816(acc[1][2 * j + 1], ah1, bh.z, bh.w);
                mma16816(acc[1][2 * j + 1], ah1, bl.z, bl.w);
                mma16816(acc[1][2 * j + 1], al1, bh.z, bh.w);
            }
        }
    }

    // ---- epilogue ----
#pragma unroll
    for (int mt = 0; mt < 2; mt++) {
        const int bp = y * WW + x0 + pq * 32 + mt * 16 + g;  // row g; +8 for row g+8
        if (MODE == 0) {
            u32* o0 = g_ts + (img * HWP + bp) * 64;
            u32* o1 = o0 + 8 * 64;
#pragma unroll
            for (int n = 0; n < 4; n++) {
                const int co0 = ch * 32 + n * 8 + 2 * tig;
                float v0 = acc[mt][n][0], v1 = acc[mt][n][1];
                float v2 = acc[mt][n][2], v3 = acc[mt][n][3];
                v0 = v0 > 0.f ? v0 : 0.1f * v0;
                v1 = v1 > 0.f ? v1 : 0.1f * v1;
                v2 = v2 > 0.f ? v2 : 0.1f * v2;
                v3 = v3 > 0.f ? v3 : 0.1f * v3;
                u32 p0 = splitpack(v0), p1 = splitpack(v1);
                u32 p2 = splitpack(v2), p3 = splitpack(v3);
                *(u64*)(o0 + co0) = (u64)p0 | ((u64)p1 << 32);
                *(u64*)(o1 + co0) = (u64)p2 | ((u64)p3 << 32);
            }
        } else {
            const float* res = (img < 2) ? (xl + img * CHW) : (xr + (img - 2) * CHW);
            float* ob = g_buf + img * CHW;
#pragma unroll
            for (int n = 0; n < 4; n++) {
                const int co0 = ch * 32 + n * 8 + 2 * tig;
                ob[co0 * HWP + bp] = acc[mt][n][0] + res[co0 * HWP + bp];
                ob[(co0 + 1) * HWP + bp] = acc[mt][n][1] + res[(co0 + 1) * HWP + bp];
                ob[co0 * HWP + bp + 8] = acc[mt][n][2] + res[co0 * HWP + bp + 8];
                ob[(co0 + 1) * HWP + bp + 8] = acc[mt][n][3] + res[(co0 + 1) * HWP + bp + 8];
            }
        }
    }
}

// ---------------- Q/S/R 1x1: smem-staged GEMM ---------------------------------
#define QSR_SMEM (32768 + 17408)
__global__ void __launch_bounds__(256, 2) qsr_k(const float* __restrict__ b1b,
                                                const float* __restrict__ b2b,
                                                const float* __restrict__ b3b) {
    extern __shared__ unsigned char dynsm[];
    u64* wsm = (u64*)dynsm;
    float* tile = (float*)(dynsm + 32768);
    float* st = (float*)(dynsm + 32768);

    const int t = threadIdx.x;
    const int mat = blockIdx.y;
    const int p0 = blockIdx.x * 256;
    const int b = p0 >> 15;
    const int lp = p0 & 32767;

    const float* in = g_buf + (((mat == 0) ? 0 : 2) + b) * CHW + lp;
    float* outp = ((mat == 0) ? g_Q : (mat == 1) ? g_S : g_R) + p0 * 64;
    const float* bias = (mat == 0) ? b1b : (mat == 1) ? b2b : b3b;

    {
        const u64* ws = g_wq[mat];
        for (int j = t; j < 4096; j += 256) wsm[j] = ws[j];
    }

    const int cg = t >> 5;
    const int tx = t & 31;

    u64 acc[8][4];
#pragma unroll
    for (int co = 0; co < 8; co++)
#pragma unroll
        for (int j = 0; j < 4; j++) acc[co][j] = 0ull;

    for (int cc0 = 0; cc0 < 64; cc0 += 16) {
        __syncthreads();
#pragma unroll
        for (int k = 0; k < 16; k++) {
            int j = t + k * 256;
            int cin = j >> 8, px = j & 255;
            tile[j] = in[(cc0 + cin) * HWP + px];
        }
        __syncthreads();
#pragma unroll 4
        for (int ci = 0; ci < 16; ci++) {
            u64 v[4];
#pragma unroll
            for (int j = 0; j < 4; j++) v[j] = *(const u64*)&tile[ci * 256 + 2 * tx + 64 * j];
            const u64* wb = wsm + (cc0 + ci) * 64 + cg * 8;
#pragma unroll
            for (int co = 0; co < 8; co++) {
                u64 w2 = wb[co];
#pragma unroll
                for (int j = 0; j < 4; j++) acc[co][j] = fma2(w2, v[j], acc[co][j]);
            }
        }
    }

#pragma unroll
    for (int j = 0; j < 4; j++) {
        __syncthreads();
#pragma unroll
        for (int co = 0; co < 8; co++) {
            float lo, hi;
            upk2(acc[co][j], lo, hi);
            st[(2 * tx) * 65 + cg * 8 + co] = lo;
            st[(2 * tx + 1) * 65 + cg * 8 + co] = hi;
        }
        __syncthreads();
        for (int i = t; i < 4096; i += 256) {
            int px = i >> 6, c = i & 63;
            outp[(64 * j + px) * 64 + c] = st[px * 65 + c] + bias[c];
        }
    }
}

// ---------------- attention: warp per pixel ----------------------------------
__global__ void __launch_bounds__(256) attn_k(const int* __restrict__ xxs,
                                              const int* __restrict__ yys,
                                              float* __restrict__ Mout) {
    const int t = threadIdx.x;
    const int lane = t & 31;
    const int p = blockIdx.x * 8 + (t >> 5);
    const int b = p >> 15;

    int fl = 0;
    if (lane < 16) fl = xxs[p * 16 + lane] * WW + yys[p * 16 + lane];

    const float q0 = g_Q[p * 64 + lane];
    const float q1 = g_Q[p * 64 + lane + 32];
    const float* Sb = g_S + b * HWP * 64;
    const float* Rb = g_R + b * HWP * 64;

    float sc[16];
    int bs[16];
#pragma unroll
    for (int k = 0; k < 16; k++) {
        int fk = __shfl_sync(0xffffffffu, fl, k);
        int base = fk * 64;
        bs[k] = base;
        float part = q0 * Sb[base + lane] + q1 * Sb[base + lane + 32];
#pragma unroll
        for (int o = 16; o; o >>= 1) part += __shfl_xor_sync(0xffffffffu, part, o);
        sc[k] = part;
    }

    float mx = sc[0];
#pragma unroll
    for (int k = 1; k < 16; k++) mx = fmaxf(mx, sc[k]);
    float sum = 0.f;
#pragma unroll
    for (int k = 0; k < 16; k++) {
        sc[k] = __expf(sc[k] - mx);
        sum += sc[k];
    }
    const float inv = 1.f / sum;

    float acc0 = 0.f, acc1 = 0.f, mv = 0.f;
#pragma unroll
    for (int k = 0; k < 16; k++) {
        float m = sc[k] * inv;
        acc0 += m * Rb[bs[k] + lane];
        acc1 += m * Rb[bs[k] + lane + 32];
        if (lane == k) mv = m;
    }

    g_battn[p * 64 + lane] = acc0;
    g_battn[p * 64 + lane + 32] = acc1;
    if (lane < 16) Mout[p * 16 + lane] = mv;
}

// ---------------- fusion 1x1 ---------------------------------------------------
#define FUSE_SMEM (65536 + 8448)
__global__ void __launch_bounds__(256) fuse_k(const float* __restrict__ xl,
                                              const float* __restrict__ fb,
                                              float* __restrict__ out) {
    extern __shared__ unsigned char dynsm[];
    u64* wsm = (u64*)dynsm;
    float* vsm = (float*)(dynsm + 65536);

    const int t = threadIdx.x;
    const int b = blockIdx.y;
    const int p0 = blockIdx.x * 256;

    for (int j = t; j < 8192; j += 256) wsm[j] = g_wfu[j];

    const float* ba = g_battn + b * HWP * 64;
    const float* xlb = xl + b * CHW;
    const int cg = t >> 6, q = t & 63;
    u64 acc[16][2];
#pragma unroll
    for (int c = 0; c < 16; c++) {
        acc[c][0] = 0ull;
        acc[c][1] = 0ull;
    }
    __syncthreads();

    for (int cc0 = 0; cc0 < 64; cc0 += 8) {
        __syncthreads();
        for (int i = t; i < 2048; i += 256) {
            int c = i & 7, px = i >> 3;
            vsm[c * 258 + px] = ba[(p0 + px) * 64 + cc0 + c];
        }
        __syncthreads();
#pragma unroll
        for (int cl = 0; cl < 8; cl++) {
            const int cin = cc0 + cl;
            u64 v0 = *(const u64*)&vsm[cl * 258 + 2 * q];
            u64 v1 = *(const u64*)&vsm[cl * 258 + 128 + 2 * q];
            const u64* wb = wsm + cin * 64 + cg * 16;
#pragma unroll
            for (int c = 0; c < 16; c++) {
                u64 w2 = wb[c];
                acc[c][0] = fma2(w2, v0, acc[c][0]);
                acc[c][1] = fma2(w2, v1, acc[c][1]);
            }
        }
    }
#pragma unroll 4
    for (int cin = 64; cin < 128; cin++) {
        u64 v0 = *(const u64*)(xlb + (cin - 64) * HWP + p0 + 2 * q);
        u64 v1 = *(const u64*)(xlb + (cin - 64) * HWP + p0 + 128 + 2 * q);
        const u64* wb = wsm + cin * 64 + cg * 16;
#pragma unroll
        for (int c = 0; c < 16; c++) {
            u64 w2 = wb[c];
            acc[c][0] = fma2(w2, v0, acc[c][0]);
            acc[c][1] = fma2(w2, v1, acc[c][1]);
        }
    }

#pragma unroll
    for (int c = 0; c < 16; c++) {
        const int co = cg * 16 + c;
        const float bb = fb[co];
#pragma unroll
        for (int r = 0; r < 2; r++) {
            float lo, hi;
            upk2(acc[c][r], lo, hi);
            float2 o;
            o.x = lo + bb;
            o.y = hi + bb;
            *(float2*)(out + (b * 64 + co) * HWP + p0 + 128 * r + 2 * q) = o;
        }
    }
}

// ---------------- launch ------------------------------------------------------
extern "C" void kernel_launch(void* const* d_in, const int* in_sizes, int n_in,
                              void* d_out, int out_size) {
    const float* xl = (const float*)d_in[0];
    const float* xr = (const float*)d_in[1];
    const int* xxs = (const int*)d_in[2];
    const int* yys = (const int*)d_in[3];
    const int wbase = (in_sizes[4] == 1) ? 5 : 4;
    const float* rb_w1 = (const float*)d_in[wbase + 0];
    const float* rb_w2 = (const float*)d_in[wbase + 1];
    const float* b1w = (const float*)d_in[wbase + 2];
    const float* b1b = (const float*)d_in[wbase + 3];
    const float* b2w = (const float*)d_in[wbase + 4];
    const float* b2b = (const float*)d_in[wbase + 5];
    const float* b3w = (const float*)d_in[wbase + 6];
    const float* b3b = (const float*)d_in[wbase + 7];
    const float* fw = (const float*)d_in[wbase + 8];
    const float* fb = (const float*)d_in[wbase + 9];

    float* out = (float*)d_out;
    float* Mout = out + BB * CC * HWP;

    cudaFuncSetAttribute(conv_mma<0>, cudaFuncAttributeMaxDynamicSharedMemorySize, CONV_SMEM);
    cudaFuncSetAttribute(conv_mma<1>, cudaFuncAttributeMaxDynamicSharedMemorySize, CONV_SMEM);
    cudaFuncSetAttribute(qsr_k, cudaFuncAttributeMaxDynamicSharedMemorySize, QSR_SMEM);
    cudaFuncSetAttribute(fuse_k, cudaFuncAttributeMaxDynamicSharedMemorySize, FUSE_SMEM);

    prep_w<<<224, 256>>>(rb_w1, rb_w2, b1w, b2w, b3w, fw);
    prep_x<<<2048, 256>>>(xl, xr);

    conv_mma<0><<<1024, 256, CONV_SMEM>>>(xl, xr);
    conv_mma<1><<<1024, 256, CONV_SMEM>>>(xl, xr);

    qsr_k<<<dim3(BB * HWP / 256, 3), 256, QSR_SMEM>>>(b1b, b2b, b3b);

    attn_k<<<BB * HWP / 8, 256>>>(xxs, yys, Mout);

    fuse_k<<<dim3(HWP / 256, BB), 256, FUSE_SMEM>>>(xl, fb, out);
}

// round 13
// speedup vs baseline: 1.8646x; 1.2251x over previous
#include <cuda_runtime.h>
#include <cuda_fp16.h>
#include <cstdint>

#define HH 128
#define WW 256
#define HWP 32768
#define CC 64
#define BB 2
#define KK 16
#define CHW (CC * HWP)

typedef unsigned long long u64;
typedef unsigned int u32;

// ---------------- scratch ----------------------------------------------------
__device__ u32 g_xs[4 * HWP * CC];   // packed {hi16,lo16} fp16 split of x, pixel-major
__device__ u32 g_ts[4 * HWP * CC];   // packed split of conv1 output
__device__ u32 g_bs[4 * HWP * CC];   // packed split of conv2 output (resblock out)
__device__ u32 g_bp[BB * HWP * CC];  // packed split of attention output
__device__ float g_Q[BB * HWP * CC];
__device__ float g_S[BB * HWP * CC];
__device__ float g_R[BB * HWP * CC];
__device__ u64 g_wf[2 * 9 * 2 * 4 * 8 * 32];  // conv B-frags (36864)
__device__ u64 g_wqf[3 * 2048];               // qsr B-frags
__device__ u64 g_wff[2 * 2048];               // fuse B-frags

// ---------------- fp16 split helpers ------------------------------------------
__device__ __forceinline__ u32 splitpack(float v) {
    __half h = __float2half_rn(v);
    __half l = __float2half_rn(v - __half2float(h));
    return (u32)__half_as_ushort(h) | ((u32)__half_as_ushort(l) << 16);
}

// ---------------- mma / ldmatrix ----------------------------------------------
__device__ __forceinline__ void mma16816(float c[4], const u32 a[4], u32 b0, u32 b1) {
    asm volatile(
        "mma.sync.aligned.m16n8k16.row.col.f32.f16.f16.f32 "
        "{%0,%1,%2,%3},{%4,%5,%6,%7},{%8,%9},{%0,%1,%2,%3};"
        : "+f"(c[0]), "+f"(c[1]), "+f"(c[2]), "+f"(c[3])
        : "r"(a[0]), "r"(a[1]), "r"(a[2]), "r"(a[3]), "r"(b0), "r"(b1));
}
__device__ __forceinline__ void ldsm4(u32 r[4], u32 addr) {
    asm volatile("ldmatrix.sync.aligned.m8n8.x4.shared.b16 {%0,%1,%2,%3}, [%4];"
                 : "=r"(r[0]), "=r"(r[1]), "=r"(r[2]), "=r"(r[3])
                 : "r"(addr));
}
__device__ __forceinline__ u32 smem_u32(const void* p) {
    u32 a;
    asm("{ .reg .u64 t; cvta.to.shared.u64 t, %1; cvt.u32.u64 %0, t; }" : "=r"(a) : "l"(p));
    return a;
}
// split a pair of packed u32 into hi-plane / lo-plane uint4 halves
__device__ __forceinline__ void split8(uint4 a, uint4 b, uint4& hv, uint4& lv) {
    hv.x = __byte_perm(a.x, a.y, 0x5410);
    hv.y = __byte_perm(a.z, a.w, 0x5410);
    hv.z = __byte_perm(b.x, b.y, 0x5410);
    hv.w = __byte_perm(b.z, b.w, 0x5410);
    lv.x = __byte_perm(a.x, a.y, 0x7632);
    lv.y = __byte_perm(a.z, a.w, 0x7632);
    lv.z = __byte_perm(b.x, b.y, 0x7632);
    lv.w = __byte_perm(b.z, b.w, 0x7632);
}

// ---------------- prep: weights ------------------------------------------------
__global__ void __launch_bounds__(256) prep_w(const float* __restrict__ w1,
                                              const float* __restrict__ w2,
                                              const float* __restrict__ qw,
                                              const float* __restrict__ sw,
                                              const float* __restrict__ rw,
                                              const float* __restrict__ fw) {
    int i = blockIdx.x * 256 + threadIdx.x;  // 0..47103
    const float* w;
    int cobase, cinstep, tapidx, split, k, low8;
    u64* dst;
    if (i < 36864) {
        int conv = i / 18432;
        int r = i % 18432;
        tapidx = r / 2048;
        int r2 = r % 2048;
        split = (r2 >> 10) & 1;
        k = (r2 >> 8) & 3;
        low8 = r2 & 255;
        w = conv ? w2 : w1;
        dst = g_wf + i;
        cobase = 64;  // marker: conv layout (w[(co*64+cin)*9+tap])
        int np = low8 >> 6, lane = (low8 >> 1) & 31, e = low8 & 1;
        int n = np * 2 + e, g = lane >> 2, tig = lane & 3;
        int co = n * 8 + g;
        unsigned short hv[4];
#pragma unroll
        for (int en = 0; en < 4; en++) {
            int cin = k * 16 + 2 * tig + (en & 1) + (en >> 1) * 8;
            float v = w[(co * 64 + cin) * 9 + tapidx];
            __half h = __float2half_rn(v);
            __half o = split ? __float2half_rn(v - __half2float(h)) : h;
            hv[en] = __half_as_ushort(o);
        }
        u32 b0 = (u32)hv[0] | ((u32)hv[1] << 16);
        u32 b1 = (u32)hv[2] | ((u32)hv[3] << 16);
        *dst = (u64)b0 | ((u64)b1 << 32);
    } else if (i < 43008) {
        // qsr frags: [mat][split][k][np][lane][e]
        int j = i - 36864;
        int mat = j / 2048;
        int r2 = j % 2048;
        split = (r2 >> 10) & 1;
        k = (r2 >> 8) & 3;
        low8 = r2 & 255;
        w = (mat == 0) ? qw : (mat == 1) ? sw : rw;
        int np = low8 >> 6, lane = (low8 >> 1) & 31, e = low8 & 1;
        int n = np * 2 + e, g = lane >> 2, tig = lane & 3;
        int co = n * 8 + g;
        unsigned short hv[4];
#pragma unroll
        for (int en = 0; en < 4; en++) {
            int cin = k * 16 + 2 * tig + (en & 1) + (en >> 1) * 8;
            float v = w[co * 64 + cin];
            __half h = __float2half_rn(v);
            __half o = split ? __float2half_rn(v - __half2float(h)) : h;
            hv[en] = __half_as_ushort(o);
        }
        u32 b0 = (u32)hv[0] | ((u32)hv[1] << 16);
        u32 b1 = (u32)hv[2] | ((u32)hv[3] << 16);
        g_wqf[j] = (u64)b0 | ((u64)b1 << 32);
    } else if (i < 47104) {
        // fuse frags: [split][k(8)][np][lane][e]
        int j = i - 43008;
        split = j >> 11;
        int r2 = j & 2047;
        k = (r2 >> 8) & 7;
        low8 = r2 & 255;
        int np = low8 >> 6, lane = (low8 >> 1) & 31, e = low8 & 1;
        int n = np * 2 + e, g = lane >> 2, tig = lane & 3;
        int co = n * 8 + g;
        unsigned short hv[4];
#pragma unroll
        for (int en = 0; en < 4; en++) {
            int cin = k * 16 + 2 * tig + (en & 1) + (en >> 1) * 8;
            float v = fw[co * 128 + cin];
            __half h = __float2half_rn(v);
            __half o = split ? __float2half_rn(v - __half2float(h)) : h;
            hv[en] = __half_as_ushort(o);
        }
        u32 b0 = (u32)hv[0] | ((u32)hv[1] << 16);
        u32 b1 = (u32)hv[2] | ((u32)hv[3] << 16);
        g_wff[j] = (u64)b0 | ((u64)b1 << 32);
    }
}

// ---------------- prep: split x into pixel-major packed u32 -------------------
__global__ void __launch_bounds__(256) prep_x(const float* __restrict__ xl,
                                              const float* __restrict__ xr) {
    __shared__ float tile[64 * 65];
    const int t = threadIdx.x;
    const int img = blockIdx.x >> 9;
    const int px0 = (blockIdx.x & 511) * 64;
    const float* in = (img < 2) ? (xl + img * CHW) : (xr + (img - 2) * CHW);

    for (int i = t; i < 4096; i += 256) {
        int cin = i >> 6, px = i & 63;
        tile[px * 65 + cin] = in[cin * HWP + px0 + px];
    }
    __syncthreads();
    for (int i = t; i < 4096; i += 256) {
        int px = i >> 6, cin = i & 63;
        g_xs[(img * HWP + px0 + px) * 64 + cin] = splitpack(tile[px * 65 + cin]);
    }
}

// ---------------- conv3x3: mma.sync, A in smem (ldsm), B via L1 LDG -----------
#define APLANE (3 * 130 * 128)        // 49920
#define CONV_SMEM (2 * APLANE)        // 99840

template <int MODE>
__global__ void __launch_bounds__(256, 2) conv_mma(const float* __restrict__ xl,
                                                   const float* __restrict__ xr) {
    extern __shared__ unsigned char sm[];
    const u32 smb = smem_u32(sm);
    const int t = threadIdx.x;
    const int w = t >> 5;
    const int lane = t & 31;
    const int g = lane >> 2, tig = lane & 3;
    const int pq = w & 3, ch = w >> 2;

    const int blk = blockIdx.x;
    const int img = blk >> 8;
    const int rr = blk & 255;
    const int y = rr >> 1;
    const int x0 = (rr & 1) * 128;

    const u32* inp = ((MODE == 0) ? g_xs : g_ts) + img * HWP * 64;

    for (int i = t; i < 3120; i += 256) {
        int gr = i & 7;
        int pxr = i >> 3;
        int r = pxr / 130, apx = pxr - r * 130;
        int gy = y - 1 + r, gx = x0 - 1 + apx;
        uint4 a = make_uint4(0, 0, 0, 0), b = make_uint4(0, 0, 0, 0);
        if ((unsigned)gy < HH && (unsigned)gx < WW) {
            const uint4* src = (const uint4*)(inp + (gy * WW + gx) * 64 + gr * 8);
            a = src[0];
            b = src[1];
        }
        uint4 hv, lv;
        split8(a, b, hv, lv);
        int base = (r * 130 + apx) * 128 + ((gr * 16) ^ ((apx & 7) << 4));
        *(uint4*)(sm + base) = hv;
        *(uint4*)(sm + APLANE + base) = lv;
    }
    __syncthreads();

    const int m = lane >> 3;
    const int rowsel = (lane & 7) + ((m & 1) << 3);
    const int colbase = (m >> 1) * 16;

    float acc[2][4][4];
#pragma unroll
    for (int mt = 0; mt < 2; mt++)
#pragma unroll
        for (int n = 0; n < 4; n++)
#pragma unroll
            for (int c = 0; c < 4; c++) acc[mt][n][c] = 0.f;

#pragma unroll
    for (int tap = 0; tap < 9; tap++) {
        const int dy = tap / 3, dx = tap - dy * 3;
        const int apx0 = pq * 32 + rowsel + dx;
        const u32 ab0 = smb + (dy * 130 + apx0) * 128;
        const u32 ab1 = ab0 + 16 * 128;
        const u32 sw = (u32)((apx0 & 7) << 4);
        const u64* WT = g_wf + (MODE * 9 + tap) * 2048 + lane * 2;

#pragma unroll
        for (int kk = 0; kk < 4; kk++) {
            u32 col = ((u32)(kk * 32 + colbase)) ^ sw;
            u32 ah0[4], al0[4], ah1[4], al1[4];
            ldsm4(ah0, ab0 + col);
            ldsm4(al0, ab0 + APLANE + col);
            ldsm4(ah1, ab1 + col);
            ldsm4(al1, ab1 + APLANE + col);
            const u64* WH = WT + kk * 256;
#pragma unroll
            for (int j = 0; j < 2; j++) {
                const u64* p = WH + (2 * ch + j) * 64;
                uint4 bh = *(const uint4*)p;
                uint4 bl = *(const uint4*)(p + 1024);
                mma16816(acc[0][2 * j], ah0, bh.x, bh.y);
                mma16816(acc[0][2 * j], ah0, bl.x, bl.y);
                mma16816(acc[0][2 * j], al0, bh.x, bh.y);
                mma16816(acc[0][2 * j + 1], ah0, bh.z, bh.w);
                mma16816(acc[0][2 * j + 1], ah0, bl.z, bl.w);
                mma16816(acc[0][2 * j + 1], al0, bh.z, bh.w);
                mma16816(acc[1][2 * j], ah1, bh.x, bh.y);
                mma16816(acc[1][2 * j], ah1, bl.x, bl.y);
                mma16816(acc[1][2 * j], al1, bh.x, bh.y);
                mma16816(acc[1][2 * j + 1], ah1, bh.z, bh.w);
                mma16816(acc[1][2 * j + 1], ah1, bl.z, bl.w);
                mma16816(acc[1][2 * j + 1], al1, bh.z, bh.w);
            }
        }
    }

    const float* res = (MODE == 1) ? ((img < 2) ? (xl + img * CHW) : (xr + (img - 2) * CHW))
                                   : (const float*)0;
#pragma unroll
    for (int mt = 0; mt < 2; mt++) {
        const int bp = y * WW + x0 + pq * 32 + mt * 16 + g;
        u32* o0 = ((MODE == 0) ? g_ts : g_bs) + (img * HWP + bp) * 64;
        u32* o1 = o0 + 8 * 64;
#pragma unroll
        for (int n = 0; n < 4; n++) {
            const int co0 = ch * 32 + n * 8 + 2 * tig;
            float v0 = acc[mt][n][0], v1 = acc[mt][n][1];
            float v2 = acc[mt][n][2], v3 = acc[mt][n][3];
            if (MODE == 0) {
                v0 = v0 > 0.f ? v0 : 0.1f * v0;
                v1 = v1 > 0.f ? v1 : 0.1f * v1;
                v2 = v2 > 0.f ? v2 : 0.1f * v2;
                v3 = v3 > 0.f ? v3 : 0.1f * v3;
            } else {
                v0 += res[co0 * HWP + bp];
                v1 += res[(co0 + 1) * HWP + bp];
                v2 += res[co0 * HWP + bp + 8];
                v3 += res[(co0 + 1) * HWP + bp + 8];
            }
            u32 p0 = splitpack(v0), p1 = splitpack(v1);
            u32 p2 = splitpack(v2), p3 = splitpack(v3);
            *(u64*)(o0 + co0) = (u64)p0 | ((u64)p1 << 32);
            *(u64*)(o1 + co0) = (u64)p2 | ((u64)p3 << 32);
        }
    }
}

// ---------------- Q/S/R 1x1 via mma --------------------------------------------
#define QPLANE 16384
#define QSR_SMEM (2 * QPLANE)

__global__ void __launch_bounds__(256, 2) qsr_mma(const float* __restrict__ b1b,
                                                  const float* __restrict__ b2b,
                                                  const float* __restrict__ b3b) {
    extern __shared__ unsigned char sm[];
    const u32 smb = smem_u32(sm);
    const int t = threadIdx.x;
    const int w = t >> 5;
    const int lane = t & 31;
    const int g = lane >> 2, tig = lane & 3;
    const int pq = w & 3, ch = w >> 2;

    const int blk = blockIdx.x;  // 0..1023
    const int img = blk >> 8;
    const int px0 = (blk & 255) * 128;
    const u32* src = g_bs + (img * HWP + px0) * 64;

    for (int i = t; i < 1024; i += 256) {
        int px = i >> 3, cc = i & 7;
        const uint4* s = (const uint4*)(src + px * 64 + cc * 8);
        uint4 a = s[0], b = s[1];
        uint4 hv, lv;
        split8(a, b, hv, lv);
        int base = px * 128 + ((cc * 16) ^ ((px & 7) << 4));
        *(uint4*)(sm + base) = hv;
        *(uint4*)(sm + QPLANE + base) = lv;
    }
    __syncthreads();

    const int m = lane >> 3;
    const int rowsel = (lane & 7) + ((m & 1) << 3);
    const int colbase = (m >> 1) * 16;
    const int apx0 = pq * 32 + rowsel;
    const u32 ab0 = smb + apx0 * 128;
    const u32 ab1 = ab0 + 16 * 128;
    const u32 sw = (u32)((apx0 & 7) << 4);

    const int npass = (img < 2) ? 1 : 2;
    for (int pass = 0; pass < npass; pass++) {
        const int mat = (img < 2) ? 0 : (1 + pass);
        const u64* WT = g_wqf + mat * 2048 + lane * 2;

        float acc[2][4][4];
#pragma unroll
        for (int mt = 0; mt < 2; mt++)
#pragma unroll
            for (int n = 0; n < 4; n++)
#pragma unroll
                for (int c = 0; c < 4; c++) acc[mt][n][c] = 0.f;

#pragma unroll
        for (int kk = 0; kk < 4; kk++) {
            u32 col = ((u32)(kk * 32 + colbase)) ^ sw;
            u32 ah0[4], al0[4], ah1[4], al1[4];
            ldsm4(ah0, ab0 + col);
            ldsm4(al0, ab0 + QPLANE + col);
            ldsm4(ah1, ab1 + col);
            ldsm4(al1, ab1 + QPLANE + col);
            const u64* WH = WT + kk * 256;
#pragma unroll
            for (int j = 0; j < 2; j++) {
                const u64* p = WH + (2 * ch + j) * 64;
                uint4 bh = *(const uint4*)p;
                uint4 bl = *(const uint4*)(p + 1024);
                mma16816(acc[0][2 * j], ah0, bh.x, bh.y);
                mma16816(acc[0][2 * j], ah0, bl.x, bl.y);
                mma16816(acc[0][2 * j], al0, bh.x, bh.y);
                mma16816(acc[0][2 * j + 1], ah0, bh.z, bh.w);
                mma16816(acc[0][2 * j + 1], ah0, bl.z, bl.w);
                mma16816(acc[0][2 * j + 1], al0, bh.z, bh.w);
                mma16816(acc[1][2 * j], ah1, bh.x, bh.y);
                mma16816(acc[1][2 * j], ah1, bl.x, bl.y);
                mma16816(acc[1][2 * j], al1, bh.x, bh.y);
                mma16816(acc[1][2 * j + 1], ah1, bh.z, bh.w);
                mma16816(acc[1][2 * j + 1], ah1, bl.z, bl.w);
                mma16816(acc[1][2 * j + 1], al1, bh.z, bh.w);
            }
        }

        const float* bias = (mat == 0) ? b1b : (mat == 1) ? b2b : b3b;
        float* outp = ((mat == 0) ? g_Q : (mat == 1) ? g_S : g_R) +
                      ((img & 1) * HWP + px0) * 64;
#pragma unroll
        for (int mt = 0; mt < 2; mt++) {
            const int prow = pq * 32 + mt * 16 + g;
#pragma unroll
            for (int n = 0; n < 4; n++) {
                const int co0 = ch * 32 + n * 8 + 2 * tig;
                float2 bb = *(const float2*)(bias + co0);
                float2 o0, o1;
                o0.x = acc[mt][n][0] + bb.x;
                o0.y = acc[mt][n][1] + bb.y;
                o1.x = acc[mt][n][2] + bb.x;
                o1.y = acc[mt][n][3] + bb.y;
                *(float2*)(outp + prow * 64 + co0) = o0;
                *(float2*)(outp + (prow + 8) * 64 + co0) = o1;
            }
        }
    }
}

// ---------------- attention: warp per pixel ----------------------------------
__global__ void __launch_bounds__(256) attn_k(const int* __restrict__ xxs,
                                              const int* __restrict__ yys,
                                              float* __restrict__ Mout) {
    const int t = threadIdx.x;
    const int lane = t & 31;
    const int p = blockIdx.x * 8 + (t >> 5);
    const int b = p >> 15;

    int fl = 0;
    if (lane < 16) fl = xxs[p * 16 + lane] * WW + yys[p * 16 + lane];

    const float q0 = g_Q[p * 64 + lane];
    const float q1 = g_Q[p * 64 + lane + 32];
    const float* Sb = g_S + b * HWP * 64;
    const float* Rb = g_R + b * HWP * 64;

    float sc[16];
    int bs[16];
#pragma unroll
    for (int k = 0; k < 16; k++) {
        int fk = __shfl_sync(0xffffffffu, fl, k);
        int base = fk * 64;
        bs[k] = base;
        float part = q0 * Sb[base + lane] + q1 * Sb[base + lane + 32];
#pragma unroll
        for (int o = 16; o; o >>= 1) part += __shfl_xor_sync(0xffffffffu, part, o);
        sc[k] = part;
    }

    float mx = sc[0];
#pragma unroll
    for (int k = 1; k < 16; k++) mx = fmaxf(mx, sc[k]);
    float sum = 0.f;
#pragma unroll
    for (int k = 0; k < 16; k++) {
        sc[k] = __expf(sc[k] - mx);
        sum += sc[k];
    }
    const float inv = 1.f / sum;

    float acc0 = 0.f, acc1 = 0.f, mv = 0.f;
#pragma unroll
    for (int k = 0; k < 16; k++) {
        float m = sc[k] * inv;
        acc0 += m * Rb[bs[k] + lane];
        acc1 += m * Rb[bs[k] + lane + 32];
        if (lane == k) mv = m;
    }

    g_bp[p * 64 + lane] = splitpack(acc0);
    g_bp[p * 64 + lane + 32] = splitpack(acc1);
    if (lane < 16) Mout[p * 16 + lane] = mv;
}

// ---------------- fusion 1x1 via mma (128 cin) --------------------------------
#define FPLANE 32768
#define FUSE_SMEM (2 * FPLANE)

__global__ void __launch_bounds__(256, 2) fuse_mma(const float* __restrict__ fb,
                                                   float* __restrict__ out) {
    extern __shared__ unsigned char sm[];
    const u32 smb = smem_u32(sm);
    const int t = threadIdx.x;
    const int w = t >> 5;
    const int lane = t & 31;
    const int g = lane >> 2, tig = lane & 3;
    const int pq = w & 3, ch = w >> 2;

    const int blk = blockIdx.x;  // 0..511
    const int b = blk >> 8;
    const int px0 = (blk & 255) * 128;
    const u32* sA = g_bp + (b * HWP + px0) * 64;  // cin 0..63 (battn)
    const u32* sX = g_xs + (b * HWP + px0) * 64;  // cin 64..127 (x_left)

    for (int i = t; i < 2048; i += 256) {
        int px = i >> 4, cc = i & 15;
        const u32* srcp = (cc < 8) ? (sA + px * 64 + cc * 8) : (sX + px * 64 + (cc - 8) * 8);
        uint4 a = ((const uint4*)srcp)[0];
        uint4 bq = ((const uint4*)srcp)[1];
        uint4 hv, lv;
        split8(a, bq, hv, lv);
        int base = px * 256 + ((cc * 16) ^ ((px & 7) << 4));
        *(uint4*)(sm + base) = hv;
        *(uint4*)(sm + FPLANE + base) = lv;
    }
    __syncthreads();

    const int m = lane >> 3;
    const int rowsel = (lane & 7) + ((m & 1) << 3);
    const int colbase = (m >> 1) * 16;
    const int apx0 = pq * 32 + rowsel;
    const u32 ab0 = smb + apx0 * 256;
    const u32 ab1 = ab0 + 16 * 256;
    const u32 sw = (u32)((apx0 & 7) << 4);

    float acc[2][4][4];
#pragma unroll
    for (int mt = 0; mt < 2; mt++)
#pragma unroll
        for (int n = 0; n < 4; n++)
#pragma unroll
            for (int c = 0; c < 4; c++) acc[mt][n][c] = 0.f;

#pragma unroll
    for (int kk = 0; kk < 8; kk++) {
        u32 col = ((u32)(kk * 32 + colbase)) ^ sw;
        u32 ah0[4], al0[4], ah1[4], al1[4];
        ldsm4(ah0, ab0 + col);
        ldsm4(al0, ab0 + FPLANE + col);
        ldsm4(ah1, ab1 + col);
        ldsm4(al1, ab1 + FPLANE + col);
        const u64* WH = g_wff + kk * 256 + lane * 2;
#pragma unroll
        for (int j = 0; j < 2; j++) {
            const u64* p = WH + (2 * ch + j) * 64;
            uint4 bh = *(const uint4*)p;
            uint4 bl = *(const uint4*)(p + 2048);
            mma16816(acc[0][2 * j], ah0, bh.x, bh.y);
            mma16816(acc[0][2 * j], ah0, bl.x, bl.y);
            mma16816(acc[0][2 * j], al0, bh.x, bh.y);
            mma16816(acc[0][2 * j + 1], ah0, bh.z, bh.w);
            mma16816(acc[0][2 * j + 1], ah0, bl.z, bl.w);
            mma16816(acc[0][2 * j + 1], al0, bh.z, bh.w);
            mma16816(acc[1][2 * j], ah1, bh.x, bh.y);
            mma16816(acc[1][2 * j], ah1, bl.x, bl.y);
            mma16816(acc[1][2 * j], al1, bh.x, bh.y);
            mma16816(acc[1][2 * j + 1], ah1, bh.z, bh.w);
            mma16816(acc[1][2 * j + 1], ah1, bl.z, bl.w);
            mma16816(acc[1][2 * j + 1], al1, bh.z, bh.w);
        }
    }

#pragma unroll
    for (int mt = 0; mt < 2; mt++) {
        const int prow = px0 + pq * 32 + mt * 16 + g;
#pragma unroll
        for (int n = 0; n < 4; n++) {
            const int co0 = ch * 32 + n * 8 + 2 * tig;
            float2 bb = *(const float2*)(fb + co0);
            out[(b * 64 + co0) * HWP + prow] = acc[mt][n][0] + bb.x;
            out[(b * 64 + co0 + 1) * HWP + prow] = acc[mt][n][1] + bb.y;
            out[(b * 64 + co0) * HWP + prow + 8] = acc[mt][n][2] + bb.x;
            out[(b * 64 + co0 + 1) * HWP + prow + 8] = acc[mt][n][3] + bb.y;
        }
    }
}

// ---------------- launch ------------------------------------------------------
extern "C" void kernel_launch(void* const* d_in, const int* in_sizes, int n_in,
                              void* d_out, int out_size) {
    const float* xl = (const float*)d_in[0];
    const float* xr = (const float*)d_in[1];
    const int* xxs = (const int*)d_in[2];
    const int* yys = (const int*)d_in[3];
    const int wbase = (in_sizes[4] == 1) ? 5 : 4;
    const float* rb_w1 = (const float*)d_in[wbase + 0];
    const float* rb_w2 = (const float*)d_in[wbase + 1];
    const float* b1w = (const float*)d_in[wbase + 2];
    const float* b1b = (const float*)d_in[wbase + 3];
    const float* b2w = (const float*)d_in[wbase + 4];
    const float* b2b = (const float*)d_in[wbase + 5];
    const float* b3w = (const float*)d_in[wbase + 6];
    const float* b3b = (const float*)d_in[wbase + 7];
    const float* fw = (const float*)d_in[wbase + 8];
    const float* fb = (const float*)d_in[wbase + 9];

    float* out = (float*)d_out;
    float* Mout = out + BB * CC * HWP;

    cudaFuncSetAttribute(conv_mma<0>, cudaFuncAttributeMaxDynamicSharedMemorySize, CONV_SMEM);
    cudaFuncSetAttribute(conv_mma<1>, cudaFuncAttributeMaxDynamicSharedMemorySize, CONV_SMEM);
    cudaFuncSetAttribute(qsr_mma, cudaFuncAttributeMaxDynamicSharedMemorySize, QSR_SMEM);
    cudaFuncSetAttribute(fuse_mma, cudaFuncAttributeMaxDynamicSharedMemorySize, FUSE_SMEM);

    prep_w<<<184, 256>>>(rb_w1, rb_w2, b1w, b2w, b3w, fw);
    prep_x<<<2048, 256>>>(xl, xr);

    conv_mma<0><<<1024, 256, CONV_SMEM>>>(xl, xr);
    conv_mma<1><<<1024, 256, CONV_SMEM>>>(xl, xr);

    qsr_mma<<<1024, 256, QSR_SMEM>>>(b1b, b2b, b3b);

    attn_k<<<BB * HWP / 8, 256>>>(xxs, yys, Mout);

    fuse_mma<<<512, 256, FUSE_SMEM>>>(fb, out);
}